// round 1
// baseline (speedup 1.0000x reference)
#include <cuda_runtime.h>
#include <math.h>

// Problem constants: D=H=W=20, V=8000, batch N=2.
// Coordinates are (x,y,z)/20, so distance = sqrt(dx^2+dy^2+dz^2)/20 with
// INTEGER dx,dy,dz. All min/max done on integer squared distances (exact),
// sqrt applied only to the final 4 maxima.

#define VV 8000
#define INF_I (1 << 28)

// Persistent device scratch (no allocations allowed).
__device__ unsigned char g_mask[2][2][VV];        // [sample][m][v], m=0: A(predict), m=1: B(target)
__device__ int           g_F2[4][VV];             // after z+y passes, per transform t = n*2+m
__device__ int           g_max2[2][2] = {{-1,-1},{-1,-1}}; // [n][0]: max over A-only of d2(.,B); [n][1]: B-only -> A
__device__ int           g_anyA[2]    = {0, 0};

// ---------------------------------------------------------------------------
// K1: one block per (transform t, x-slab). Computes mask bits, then the z-pass
// and y-pass of the separable squared-EDT entirely in shared memory.
// ---------------------------------------------------------------------------
__global__ void k1_mask_zy(const float* __restrict__ predict,
                           const float* __restrict__ target)
{
    int b = blockIdx.x;             // 0..79 : t*20 + x
    int t = b / 20, x = b % 20;
    int n = t >> 1, m = t & 1;
    const float* src = (m == 0 ? predict : target) + n * VV + x * 400;

    __shared__ unsigned char mk[400];
    __shared__ int F1[400];
    int tid = threadIdx.x;

    if (tid < 400) {
        // jnp.round is round-half-even; rintf matches.
        unsigned char bit = (rintf(src[tid]) != 0.0f) ? 1 : 0;
        mk[tid] = bit;
        g_mask[n][m][x * 400 + tid] = bit;
    }
    __syncthreads();

    if (tid < 400) {
        int y = tid / 20, z = tid % 20;
        int best = INF_I;
        #pragma unroll
        for (int zp = 0; zp < 20; zp++) {
            int dz = z - zp;
            int cand = mk[y * 20 + zp] ? dz * dz : INF_I;
            best = min(best, cand);
        }
        F1[tid] = best;
    }
    __syncthreads();

    if (tid < 400) {
        int y = tid / 20, z = tid % 20;
        int best = INF_I;
        #pragma unroll
        for (int yp = 0; yp < 20; yp++) {
            int dy = y - yp;
            best = min(best, F1[yp * 20 + z] + dy * dy);
        }
        g_F2[t][x * 400 + tid] = best;
    }
}

// ---------------------------------------------------------------------------
// K2: x-pass of the EDT (finishing min_{u in set} d2(v,u)) + masked max
// reductions. Block-local reduction via SMEM atomics, then one global
// atomicMax per block per counter.
// ---------------------------------------------------------------------------
__global__ void k2_x_reduce()
{
    __shared__ int smax[2][2];
    __shared__ int sany[2];
    if (threadIdx.x < 4) smax[threadIdx.x >> 1][threadIdx.x & 1] = -1;
    if (threadIdx.x < 2) sany[threadIdx.x] = 0;
    __syncthreads();

    int c = blockIdx.x * blockDim.x + threadIdx.x;   // 0..31999
    if (c < 4 * VV) {
        int t = c / VV, v = c % VV;
        int n = t >> 1, m = t & 1;
        int x = v / 400, yz = v % 400;
        const int* f2 = g_F2[t];
        int best = INF_I;
        #pragma unroll
        for (int xp = 0; xp < 20; xp++) {
            int dx = x - xp;
            best = min(best, f2[xp * 400 + yz] + dx * dx);
        }
        int mA = g_mask[n][0][v];
        int mB = g_mask[n][1][v];
        if (m == 1) {
            // transform t = min distance to B; candidate for distA over A-only points
            if (mA && !mB) atomicMax(&smax[n][0], best);
        } else {
            // transform t = min distance to A; candidate for distB over B-only points
            if (mB && !mA) atomicMax(&smax[n][1], best);
            if (mA) sany[n] = 1;   // benign race: all writers store 1
        }
    }
    __syncthreads();

    if (threadIdx.x < 4) {
        int val = smax[threadIdx.x >> 1][threadIdx.x & 1];
        if (val >= 0) atomicMax(&g_max2[threadIdx.x >> 1][threadIdx.x & 1], val);
    }
    if (threadIdx.x < 2) {
        if (sany[threadIdx.x]) atomicOr(&g_anyA[threadIdx.x], 1);
    }
}

// ---------------------------------------------------------------------------
// K3: finalize (special cases exactly as reference), write output, and reset
// the accumulators to their static-init values so every kernel_launch call /
// graph replay is identical.
// ---------------------------------------------------------------------------
__global__ void k3_final(float* __restrict__ out)
{
    float s = 0.0f;
    #pragma unroll
    for (int n = 0; n < 2; n++) {
        int a2 = g_max2[n][0];
        int b2 = g_max2[n][1];
        int anyA = g_anyA[n];
        // distA: 0 if no A-only points; BIG (1e9) if B empty (a2 >= INF-ish)
        float distA = 0.0f;
        if (a2 >= 0) distA = (a2 > 3 * 19 * 19) ? 1e9f : sqrtf((float)a2) * (1.0f / 20.0f);
        // distB: 0 if no B-only points; 999 if A empty; else sqrt/20
        float distB = 0.0f;
        if (b2 >= 0) distB = anyA ? sqrtf((float)b2) * (1.0f / 20.0f) : 999.0f;
        s += fmaxf(distA, distB);
        g_max2[n][0] = -1; g_max2[n][1] = -1; g_anyA[n] = 0;
    }
    out[0] = s * 0.5f;
}

extern "C" void kernel_launch(void* const* d_in, const int* in_sizes, int n_in,
                              void* d_out, int out_size)
{
    const float* predict = (const float*)d_in[0];
    const float* target  = (const float*)d_in[1];
    float* out = (float*)d_out;

    k1_mask_zy<<<80, 416>>>(predict, target);
    k2_x_reduce<<<125, 256>>>();
    k3_final<<<1, 1>>>(out);
}